// round 9
// baseline (speedup 1.0000x reference)
#include <cuda_runtime.h>
#include <cuda_bf16.h>
#include <math.h>
#include <stdint.h>

// ---------------------------------------------------------------------------
// Problem constants
// ---------------------------------------------------------------------------
#define T_SEQ 2048
#define HID   3584
#define NH    16
#define NKV   8
#define HD    256
#define QKV_COLS ((NH + 2 * NKV) * HD)   // 8192
#define K_OFF (NH * HD)                  // 4096
#define V_OFF ((NH + NKV) * HD)          // 6144
#define ATTN_COLS (NH * HD)              // 4096

#define SOFT_CAP 50.0f
#define ATTN_SCALE 0.0625f               // 256^-0.5
#define NEG_INF __int_as_float(0xff800000)

// ---------------------------------------------------------------------------
// Static device scratch
// ---------------------------------------------------------------------------
__device__ float g_qkv[(size_t)T_SEQ * QKV_COLS];              // fp32 qkv
__device__ float g_scores[(size_t)NH * T_SEQ * T_SEQ];         // fp32 scores

__device__ __nv_bfloat16 g_hc_h[(size_t)T_SEQ * HID];
__device__ __nv_bfloat16 g_hc_l[(size_t)T_SEQ * HID];
__device__ __nv_bfloat16 g_wqkvT_h[(size_t)QKV_COLS * HID];
__device__ __nv_bfloat16 g_wqkvT_l[(size_t)QKV_COLS * HID];
__device__ __nv_bfloat16 g_woT_h[(size_t)HID * ATTN_COLS];
__device__ __nv_bfloat16 g_woT_l[(size_t)HID * ATTN_COLS];
__device__ __nv_bfloat16 g_qkvc_h[(size_t)T_SEQ * QKV_COLS];
__device__ __nv_bfloat16 g_qkvc_l[(size_t)T_SEQ * QKV_COLS];
__device__ __nv_bfloat16 g_vTc_h[(size_t)NKV * HD * T_SEQ];
__device__ __nv_bfloat16 g_vTc_l[(size_t)NKV * HD * T_SEQ];
__device__ __nv_bfloat16 g_p_h[(size_t)NH * T_SEQ * T_SEQ];
__device__ __nv_bfloat16 g_p_l[(size_t)NH * T_SEQ * T_SEQ];
__device__ __nv_bfloat16 g_attnc_h[(size_t)T_SEQ * ATTN_COLS];
__device__ __nv_bfloat16 g_attnc_l[(size_t)T_SEQ * ATTN_COLS];

// ---------------------------------------------------------------------------
// PTX helpers
// ---------------------------------------------------------------------------
__device__ __forceinline__ uint32_t smem_u32(const void* p) {
    uint32_t a;
    asm("{ .reg .u64 t; cvta.to.shared.u64 t, %1; cvt.u32.u64 %0, t; }" : "=r"(a) : "l"(p));
    return a;
}
__device__ __forceinline__ void ldgsts16(uint32_t s, const void* g) {
    asm volatile("cp.async.cg.shared.global [%0], [%1], 16;" :: "r"(s), "l"(g));
}
__device__ __forceinline__ void ldsm4(uint32_t* r, uint32_t a) {
    asm volatile("ldmatrix.sync.aligned.m8n8.x4.shared.b16 {%0,%1,%2,%3}, [%4];"
        : "=r"(r[0]), "=r"(r[1]), "=r"(r[2]), "=r"(r[3]) : "r"(a));
}
__device__ __forceinline__ void mma16816(float* d, const uint32_t* a, const uint32_t* b) {
    asm volatile("mma.sync.aligned.m16n8k16.row.col.f32.bf16.bf16.f32 "
        "{%0,%1,%2,%3}, {%4,%5,%6,%7}, {%8,%9}, {%0,%1,%2,%3};"
        : "+f"(d[0]), "+f"(d[1]), "+f"(d[2]), "+f"(d[3])
        : "r"(a[0]), "r"(a[1]), "r"(a[2]), "r"(a[3]), "r"(b[0]), "r"(b[1]));
}

// ---------------------------------------------------------------------------
// HMMA GEMM (R3 core + 3-stage pipeline):  C[z] = A[z] @ B[z/bDiv]^T
//   3-pass split accumulation: AhBh + AhBl + AlBh (fp32 accum)
//   256 threads (8 warps, 2x4), warp tile 64x32, BM=BN=128, BK=64,
//   3-stage cp.async pipeline (two loads in flight during compute),
//   1 CTA/SM (regs ~190, no spills).
// EPI: 0 = fp32 store; 1 = scores softcap; 2 = split-bf16 pair store
// CAUSAL: 1 = skip tiles above diagonal; 2 = truncate K at diagonal
// ---------------------------------------------------------------------------
#define NSTAGE  3
#define STAGE_B 65536                    // Ah 16K | Al 16K | Bh 16K | Bl 16K
#define GEMM_SMEM (NSTAGE * STAGE_B + 1024)

template<int EPI, int CAUSAL>
__global__ void __launch_bounds__(256)
gemm_mma(const __nv_bfloat16* __restrict__ Ah, const __nv_bfloat16* __restrict__ Al,
         const __nv_bfloat16* __restrict__ Bh, const __nv_bfloat16* __restrict__ Bl,
         float* __restrict__ C, __nv_bfloat16* __restrict__ Ch, __nv_bfloat16* __restrict__ Cl,
         int K, int lda, int ldb, int ldc,
         long long sA, long long sB, long long sC, int bDiv)
{
    extern __shared__ char dsm[];
    const int tid  = threadIdx.x;
    const int wid  = tid >> 5;
    const int lane = tid & 31;
    const int row0 = blockIdx.y * 128;
    const int col0 = blockIdx.x * 128;

    if (CAUSAL == 1 && col0 >= row0 + 128) return;   // fully masked: never computed

    const long long z = blockIdx.z;
    Ah += z * sA;  Al += z * sA;
    Bh += (z / bDiv) * sB;  Bl += (z / bDiv) * sB;

    const uint32_t raw = smem_u32(dsm);
    const uint32_t sb0 = (raw + 1023) & ~1023u;

    int nCh = K >> 6;
    if (CAUSAL == 2) { int lim = (row0 >> 6) + 2; if (lim < nCh) nCh = lim; }

    float acc[4][4][4];
    #pragma unroll
    for (int a = 0; a < 4; a++)
        #pragma unroll
        for (int b = 0; b < 4; b++)
            #pragma unroll
            for (int c = 0; c < 4; c++) acc[a][b][c] = 0.0f;

    const int m0w = (wid & 1) * 64;
    const int n0w = (wid >> 1) * 32;
    const int aRowL = lane & 15;
    const int aColL = (lane >> 4) << 3;
    const int bRowL = (lane & 7) + ((lane >> 4) << 3);
    const int bColL = ((lane >> 3) & 1) << 3;

    // stage loader: 4 arrays x 128 rows x 64 bf16 (128B rows, SW128 swizzle)
    auto issue = [&](int ic) {
        const int k0 = ic << 6;
        const uint32_t st = sb0 + (ic % NSTAGE) * STAGE_B;
        #pragma unroll
        for (int i = 0; i < 4; i++) {
            int t = tid + i * 256;
            int r = t >> 3, chn = t & 7;
            uint32_t off = (uint32_t)(r * 128 + chn * 16);
            off ^= (off >> 3) & 0x70;
            long long ga = (long long)(row0 + r) * lda + k0 + chn * 8;
            long long gb = (long long)(col0 + r) * ldb + k0 + chn * 8;
            ldgsts16(st + off,         Ah + ga);
            ldgsts16(st + 16384 + off, Al + ga);
            ldgsts16(st + 32768 + off, Bh + gb);
            ldgsts16(st + 49152 + off, Bl + gb);
        }
    };

    issue(0);
    asm volatile("cp.async.commit_group;" ::: "memory");
    if (nCh > 1) issue(1);
    asm volatile("cp.async.commit_group;" ::: "memory");

    for (int ic = 0; ic < nCh; ic++) {
        asm volatile("cp.async.wait_group 1;" ::: "memory");
        __syncthreads();
        if (ic + 2 < nCh) issue(ic + 2);
        asm volatile("cp.async.commit_group;" ::: "memory");

        const uint32_t st = sb0 + (ic % NSTAGE) * STAGE_B;
        #pragma unroll
        for (int ks = 0; ks < 4; ks++) {
            const int k0e = ks * 16;
            uint32_t ah[4][4], al[4][4], bh[2][4], bl[2][4];
            #pragma unroll
            for (int mt = 0; mt < 4; mt++) {
                uint32_t off = (uint32_t)((m0w + mt * 16 + aRowL) * 128 + (k0e + aColL) * 2);
                off ^= (off >> 3) & 0x70;
                ldsm4(ah[mt], st + off);
            }
            #pragma unroll
            for (int p = 0; p < 2; p++) {
                uint32_t off = (uint32_t)((n0w + p * 16 + bRowL) * 128 + (k0e + bColL) * 2);
                off ^= (off >> 3) & 0x70;
                ldsm4(bh[p], st + 32768 + off);
            }
            #pragma unroll
            for (int mt = 0; mt < 4; mt++)
                #pragma unroll
                for (int nt = 0; nt < 4; nt++)
                    mma16816(acc[mt][nt], ah[mt], &bh[nt >> 1][(nt & 1) * 2]);

            #pragma unroll
            for (int p = 0; p < 2; p++) {
                uint32_t off = (uint32_t)((n0w + p * 16 + bRowL) * 128 + (k0e + bColL) * 2);
                off ^= (off >> 3) & 0x70;
                ldsm4(bl[p], st + 49152 + off);
            }
            #pragma unroll
            for (int mt = 0; mt < 4; mt++)
                #pragma unroll
                for (int nt = 0; nt < 4; nt++)
                    mma16816(acc[mt][nt], ah[mt], &bl[nt >> 1][(nt & 1) * 2]);

            #pragma unroll
            for (int mt = 0; mt < 4; mt++) {
                uint32_t off = (uint32_t)((m0w + mt * 16 + aRowL) * 128 + (k0e + aColL) * 2);
                off ^= (off >> 3) & 0x70;
                ldsm4(al[mt], st + 16384 + off);
            }
            #pragma unroll
            for (int mt = 0; mt < 4; mt++)
                #pragma unroll
                for (int nt = 0; nt < 4; nt++)
                    mma16816(acc[mt][nt], al[mt], &bh[nt >> 1][(nt & 1) * 2]);
        }
    }

    // ---- register epilogue
    if (EPI <= 1) C += z * sC;
    else { Ch += z * sC; Cl += z * sC; }

    #pragma unroll
    for (int mt = 0; mt < 4; mt++) {
        #pragma unroll
        for (int nt = 0; nt < 4; nt++) {
            const int r = row0 + m0w + mt * 16 + (lane >> 2);
            const int c = col0 + n0w + nt * 8 + (lane & 3) * 2;
            float d0 = acc[mt][nt][0], d1 = acc[mt][nt][1];
            float d2 = acc[mt][nt][2], d3 = acc[mt][nt][3];
            if (EPI == 1) {
                d0 = SOFT_CAP * tanhf(d0 * (ATTN_SCALE / SOFT_CAP));
                d1 = SOFT_CAP * tanhf(d1 * (ATTN_SCALE / SOFT_CAP));
                d2 = SOFT_CAP * tanhf(d2 * (ATTN_SCALE / SOFT_CAP));
                d3 = SOFT_CAP * tanhf(d3 * (ATTN_SCALE / SOFT_CAP));
            }
            if (EPI <= 1) {
                *reinterpret_cast<float2*>(C + (long long)r * ldc + c)       = make_float2(d0, d1);
                *reinterpret_cast<float2*>(C + (long long)(r + 8) * ldc + c) = make_float2(d2, d3);
            } else {
                __nv_bfloat16 h0 = __float2bfloat16(d0), h1 = __float2bfloat16(d1);
                __nv_bfloat16 h2 = __float2bfloat16(d2), h3 = __float2bfloat16(d3);
                __nv_bfloat162 hv0(h0, h1), hv1(h2, h3);
                __nv_bfloat162 lv0(__float2bfloat16(d0 - __bfloat162float(h0)),
                                   __float2bfloat16(d1 - __bfloat162float(h1)));
                __nv_bfloat162 lv1(__float2bfloat16(d2 - __bfloat162float(h2)),
                                   __float2bfloat16(d3 - __bfloat162float(h3)));
                *reinterpret_cast<__nv_bfloat162*>(Ch + (long long)r * ldc + c)       = hv0;
                *reinterpret_cast<__nv_bfloat162*>(Cl + (long long)r * ldc + c)       = lv0;
                *reinterpret_cast<__nv_bfloat162*>(Ch + (long long)(r + 8) * ldc + c) = hv1;
                *reinterpret_cast<__nv_bfloat162*>(Cl + (long long)(r + 8) * ldc + c) = lv1;
            }
        }
    }
}

// ---------------------------------------------------------------------------
// fp32 -> (hi, lo) bf16 split, elementwise
// ---------------------------------------------------------------------------
__global__ void __launch_bounds__(256)
convsplit(const float4* __restrict__ x, __nv_bfloat162* __restrict__ hi,
          __nv_bfloat162* __restrict__ lo, long long n4)
{
    long long i = (long long)blockIdx.x * 256 + threadIdx.x;
    if (i >= n4) return;
    float4 v = x[i];
    __nv_bfloat16 h0 = __float2bfloat16(v.x), h1 = __float2bfloat16(v.y);
    __nv_bfloat16 h2 = __float2bfloat16(v.z), h3 = __float2bfloat16(v.w);
    hi[2 * i]     = __nv_bfloat162(h0, h1);
    hi[2 * i + 1] = __nv_bfloat162(h2, h3);
    lo[2 * i]     = __nv_bfloat162(__float2bfloat16(v.x - __bfloat162float(h0)),
                                   __float2bfloat16(v.y - __bfloat162float(h1)));
    lo[2 * i + 1] = __nv_bfloat162(__float2bfloat16(v.z - __bfloat162float(h2)),
                                   __float2bfloat16(v.w - __bfloat162float(h3)));
}

// ---------------------------------------------------------------------------
// Transpose + split: in[R,C] fp32 (ldin) -> out[C,R] (hi, lo) bf16 (ldout)
// ---------------------------------------------------------------------------
__global__ void __launch_bounds__(256)
tsplit(const float* __restrict__ in, int ldin, __nv_bfloat16* __restrict__ oh,
       __nv_bfloat16* __restrict__ ol, int ldout)
{
    __shared__ float t[32][33];
    int bx = blockIdx.x * 32, by = blockIdx.y * 32;
    int tx = threadIdx.x, ty = threadIdx.y;
    #pragma unroll
    for (int j = ty; j < 32; j += 8)
        t[j][tx] = in[(long long)(by + j) * ldin + bx + tx];
    __syncthreads();
    #pragma unroll
    for (int j = ty; j < 32; j += 8) {
        float v = t[tx][j];
        __nv_bfloat16 h = __float2bfloat16(v);
        long long o = (long long)(bx + j) * ldout + by + tx;
        oh[o] = h;
        ol[o] = __float2bfloat16(v - __bfloat162float(h));
    }
}

// ---------------------------------------------------------------------------
// Fused RoPE + split: reads fp32 qkv (Q,K region), writes split bf16 pair
// ---------------------------------------------------------------------------
__global__ void __launch_bounds__(256)
rope_split(const float* __restrict__ qkv, const int* __restrict__ positions,
           __nv_bfloat16* __restrict__ oh, __nv_bfloat16* __restrict__ ol)
{
    int idx = blockIdx.x * blockDim.x + threadIdx.x;
    int i = idx & 127;
    int h = (idx >> 7) % (NH + NKV);
    int t = idx / (128 * (NH + NKV));
    if (t >= T_SEQ) return;
    float pos = (float)positions[t];
    float inv = powf(10000.0f, -((2.0f * (float)i) / (float)HD));
    float f = pos * inv;
    float c, s;
    sincosf(f, &s, &c);
    long long base = (long long)t * QKV_COLS + h * HD;   // h<24 covers Q then K region
    float x1 = qkv[base + i], x2 = qkv[base + i + HD / 2];
    float y1 = x1 * c - x2 * s;
    float y2 = x2 * c + x1 * s;
    __nv_bfloat16 h1 = __float2bfloat16(y1);
    __nv_bfloat16 h2 = __float2bfloat16(y2);
    oh[base + i]          = h1;
    ol[base + i]          = __float2bfloat16(y1 - __bfloat162float(h1));
    oh[base + i + HD / 2] = h2;
    ol[base + i + HD / 2] = __float2bfloat16(y2 - __bfloat162float(h2));
}

// ---------------------------------------------------------------------------
// Causal softmax, single global read (registers cache the row),
// __expf (MUFU) for exponentials, split probs zero-padded to tile boundary.
// ---------------------------------------------------------------------------
__global__ void __launch_bounds__(256)
softmax3(const float* __restrict__ s, __nv_bfloat16* __restrict__ ph,
         __nv_bfloat16* __restrict__ pl)
{
    const int q = blockIdx.x;
    long long ro = ((long long)blockIdx.y * T_SEQ + q) * (long long)T_SEQ;
    const int len = q + 1;
    const int padEnd = ((q >> 7) + 1) << 7;
    const int tid = threadIdx.x, lane = tid & 31, wid = tid >> 5;
    __shared__ float red[8];

    float v[8];
    #pragma unroll
    for (int j = 0; j < 8; j++) {
        int i = tid + j * 256;
        v[j] = (i < len) ? s[ro + i] : NEG_INF;
    }
    float m = NEG_INF;
    #pragma unroll
    for (int j = 0; j < 8; j++) m = fmaxf(m, v[j]);
    #pragma unroll
    for (int o = 16; o; o >>= 1) m = fmaxf(m, __shfl_xor_sync(0xffffffffu, m, o));
    if (lane == 0) red[wid] = m;
    __syncthreads();
    if (tid < 8) {
        float x = red[tid];
        #pragma unroll
        for (int o = 4; o; o >>= 1) x = fmaxf(x, __shfl_xor_sync(0xffu, x, o));
        if (tid == 0) red[0] = x;
    }
    __syncthreads();
    m = red[0];
    __syncthreads();

    float e[8];
    float sum = 0.0f;
    #pragma unroll
    for (int j = 0; j < 8; j++) {
        e[j] = (v[j] == NEG_INF) ? 0.0f : __expf(v[j] - m);
        sum += e[j];
    }
    #pragma unroll
    for (int o = 16; o; o >>= 1) sum += __shfl_xor_sync(0xffffffffu, sum, o);
    if (lane == 0) red[wid] = sum;
    __syncthreads();
    if (tid < 8) {
        float x = red[tid];
        #pragma unroll
        for (int o = 4; o; o >>= 1) x += __shfl_xor_sync(0xffu, x, o);
        if (tid == 0) red[0] = x;
    }
    __syncthreads();
    float inv = 1.0f / red[0];

    #pragma unroll
    for (int j = 0; j < 8; j++) {
        int i = tid + j * 256;
        if (i < padEnd) {
            float p = e[j] * inv;                 // 0 beyond len
            __nv_bfloat16 h = __float2bfloat16(p);
            ph[ro + i] = h;
            pl[ro + i] = __float2bfloat16(p - __bfloat162float(h));
        }
    }
}

// ---------------------------------------------------------------------------
// kernel_launch — graph-capturable, allocation-free
// ---------------------------------------------------------------------------
extern "C" void kernel_launch(void* const* d_in, const int* in_sizes, int n_in,
                              void* d_out, int out_size)
{
    const int*   positions = (const int*)  d_in[0];
    const float* hidden    = (const float*)d_in[1];
    const float* w_qkv     = (const float*)d_in[2];
    const float* w_o       = (const float*)d_in[3];
    float*       out       = (float*)d_out;

    float *qkv, *scores;
    __nv_bfloat16 *hch, *hcl, *wqh, *wql, *woh, *wol, *qch, *qcl, *vch, *vcl, *pph, *ppl, *ach, *acl;
    cudaGetSymbolAddress((void**)&qkv,    g_qkv);
    cudaGetSymbolAddress((void**)&scores, g_scores);
    cudaGetSymbolAddress((void**)&hch, g_hc_h);    cudaGetSymbolAddress((void**)&hcl, g_hc_l);
    cudaGetSymbolAddress((void**)&wqh, g_wqkvT_h); cudaGetSymbolAddress((void**)&wql, g_wqkvT_l);
    cudaGetSymbolAddress((void**)&woh, g_woT_h);   cudaGetSymbolAddress((void**)&wol, g_woT_l);
    cudaGetSymbolAddress((void**)&qch, g_qkvc_h);  cudaGetSymbolAddress((void**)&qcl, g_qkvc_l);
    cudaGetSymbolAddress((void**)&vch, g_vTc_h);   cudaGetSymbolAddress((void**)&vcl, g_vTc_l);
    cudaGetSymbolAddress((void**)&pph, g_p_h);     cudaGetSymbolAddress((void**)&ppl, g_p_l);
    cudaGetSymbolAddress((void**)&ach, g_attnc_h); cudaGetSymbolAddress((void**)&acl, g_attnc_l);

    cudaFuncSetAttribute(gemm_mma<0, 0>, cudaFuncAttributeMaxDynamicSharedMemorySize, GEMM_SMEM);
    cudaFuncSetAttribute(gemm_mma<1, 1>, cudaFuncAttributeMaxDynamicSharedMemorySize, GEMM_SMEM);
    cudaFuncSetAttribute(gemm_mma<2, 2>, cudaFuncAttributeMaxDynamicSharedMemorySize, GEMM_SMEM);

    // Operand prep
    tsplit<<<dim3(QKV_COLS / 32, HID / 32), dim3(32, 8)>>>(w_qkv, QKV_COLS, wqh, wql, HID);
    tsplit<<<dim3(HID / 32, ATTN_COLS / 32), dim3(32, 8)>>>(w_o, HID, woh, wol, ATTN_COLS);
    {
        long long n4 = (long long)T_SEQ * HID / 4;
        convsplit<<<(unsigned)((n4 + 255) / 256), 256>>>((const float4*)hidden,
            (__nv_bfloat162*)hch, (__nv_bfloat162*)hcl, n4);
    }

    // 1) QKV projection -> fp32 qkv
    gemm_mma<0, 0><<<dim3(QKV_COLS / 128, T_SEQ / 128, 1), 256, GEMM_SMEM>>>(
        hch, hcl, wqh, wql, qkv, nullptr, nullptr,
        HID, HID, HID, QKV_COLS, 0, 0, 0, 1);

    // 2) fused RoPE + split on Q,K;  transpose+split V
    rope_split<<<(T_SEQ * (NH + NKV) * (HD / 2)) / 256, 256>>>(qkv, positions, qch, qcl);
    tsplit<<<dim3((NKV * HD) / 32, T_SEQ / 32), dim3(32, 8)>>>(qkv + V_OFF, QKV_COLS, vch, vcl, T_SEQ);

    // 3) scores[h] = softcap(scale * Q_h K_{h/2}^T), upper tiles skipped
    gemm_mma<1, 1><<<dim3(T_SEQ / 128, T_SEQ / 128, NH), 256, GEMM_SMEM>>>(
        qch, qcl, qch + K_OFF, qcl + K_OFF, scores, nullptr, nullptr,
        HD, QKV_COLS, QKV_COLS, T_SEQ,
        (long long)HD, (long long)HD, (long long)T_SEQ * T_SEQ, 2);

    // 4) causal softmax -> split probs (zero-padded to tile boundary)
    softmax3<<<dim3(T_SEQ, NH), 256>>>(scores, pph, ppl);

    // 5) attn[h] = P_h @ V_{h/2}, K truncated at diagonal; direct split store
    gemm_mma<2, 2><<<dim3(HD / 128, T_SEQ / 128, NH), 256, GEMM_SMEM>>>(
        pph, ppl, vch, vcl, nullptr, ach, acl,
        T_SEQ, T_SEQ, T_SEQ, ATTN_COLS,
        (long long)T_SEQ * T_SEQ, (long long)HD * T_SEQ, (long long)HD, 2);

    // 6) output projection
    gemm_mma<0, 0><<<dim3(HID / 128, T_SEQ / 128, 1), 256, GEMM_SMEM>>>(
        ach, acl, woh, wol, out, nullptr, nullptr,
        ATTN_COLS, ATTN_COLS, ATTN_COLS, HID, 0, 0, 0, 1);
}

// round 11
// speedup vs baseline: 1.5710x; 1.5710x over previous
#include <cuda_runtime.h>
#include <cuda_bf16.h>
#include <math.h>
#include <stdint.h>

// ---------------------------------------------------------------------------
// Problem constants
// ---------------------------------------------------------------------------
#define T_SEQ 2048
#define HID   3584
#define NH    16
#define NKV   8
#define HD    256
#define QKV_COLS ((NH + 2 * NKV) * HD)   // 8192
#define K_OFF (NH * HD)                  // 4096
#define V_OFF ((NH + NKV) * HD)          // 6144
#define ATTN_COLS (NH * HD)              // 4096

#define SOFT_CAP 50.0f
#define ATTN_SCALE 0.0625f               // 256^-0.5
#define NEG_INF __int_as_float(0xff800000)

// ---------------------------------------------------------------------------
// Static device scratch
// ---------------------------------------------------------------------------
__device__ float g_qkv[(size_t)T_SEQ * QKV_COLS];              // fp32 qkv
__device__ float g_scores[(size_t)NH * T_SEQ * T_SEQ];         // fp32 scores

__device__ __nv_bfloat16 g_hc_h[(size_t)T_SEQ * HID];
__device__ __nv_bfloat16 g_hc_l[(size_t)T_SEQ * HID];
__device__ __nv_bfloat16 g_wqkvT_h[(size_t)QKV_COLS * HID];
__device__ __nv_bfloat16 g_wqkvT_l[(size_t)QKV_COLS * HID];
__device__ __nv_bfloat16 g_woT_h[(size_t)HID * ATTN_COLS];
__device__ __nv_bfloat16 g_woT_l[(size_t)HID * ATTN_COLS];
__device__ __nv_bfloat16 g_qkvc_h[(size_t)T_SEQ * QKV_COLS];
__device__ __nv_bfloat16 g_qkvc_l[(size_t)T_SEQ * QKV_COLS];
__device__ __nv_bfloat16 g_vTc_h[(size_t)NKV * HD * T_SEQ];
__device__ __nv_bfloat16 g_vTc_l[(size_t)NKV * HD * T_SEQ];
__device__ __nv_bfloat16 g_p_h[(size_t)NH * T_SEQ * T_SEQ];
__device__ __nv_bfloat16 g_p_l[(size_t)NH * T_SEQ * T_SEQ];
__device__ __nv_bfloat16 g_attnc_h[(size_t)T_SEQ * ATTN_COLS];
__device__ __nv_bfloat16 g_attnc_l[(size_t)T_SEQ * ATTN_COLS];

// ---------------------------------------------------------------------------
// PTX helpers
// ---------------------------------------------------------------------------
__device__ __forceinline__ uint32_t smem_u32(const void* p) {
    uint32_t a;
    asm("{ .reg .u64 t; cvta.to.shared.u64 t, %1; cvt.u32.u64 %0, t; }" : "=r"(a) : "l"(p));
    return a;
}
__device__ __forceinline__ void ldgsts16(uint32_t s, const void* g) {
    asm volatile("cp.async.cg.shared.global [%0], [%1], 16;" :: "r"(s), "l"(g));
}
__device__ __forceinline__ void ldsm4(uint32_t* r, uint32_t a) {
    asm volatile("ldmatrix.sync.aligned.m8n8.x4.shared.b16 {%0,%1,%2,%3}, [%4];"
        : "=r"(r[0]), "=r"(r[1]), "=r"(r[2]), "=r"(r[3]) : "r"(a));
}
__device__ __forceinline__ void mma16816(float* d, const uint32_t* a, const uint32_t* b) {
    asm volatile("mma.sync.aligned.m16n8k16.row.col.f32.bf16.bf16.f32 "
        "{%0,%1,%2,%3}, {%4,%5,%6,%7}, {%8,%9}, {%0,%1,%2,%3};"
        : "+f"(d[0]), "+f"(d[1]), "+f"(d[2]), "+f"(d[3])
        : "r"(a[0]), "r"(a[1]), "r"(a[2]), "r"(a[3]), "r"(b[0]), "r"(b[1]));
}

// ---------------------------------------------------------------------------
// HMMA GEMM (exact R3 core):  C[z] = A[z] @ B[z/bDiv]^T
//   3-pass split accumulation: AhBh + AhBl + AlBh (fp32 accum)
//   256 threads (8 warps 2x4), warp tile 64x32, BM=BN=128, BK=64,
//   2-stage cp.async double buffer, 1 CTA/SM.
// EPI: 0 = fp32 store; 1 = scores softcap; 2 = split-bf16 pair store
// CAUSAL: 1 = skip tiles above diagonal; 2 = truncate K at diagonal
// ---------------------------------------------------------------------------
#define STAGE_B 65536                    // Ah 16K | Al 16K | Bh 16K | Bl 16K
#define GEMM_SMEM (2 * STAGE_B + 1024)

template<int EPI, int CAUSAL>
__global__ void __launch_bounds__(256, 1)
gemm_mma(const __nv_bfloat16* __restrict__ Ah, const __nv_bfloat16* __restrict__ Al,
         const __nv_bfloat16* __restrict__ Bh, const __nv_bfloat16* __restrict__ Bl,
         float* __restrict__ C, __nv_bfloat16* __restrict__ Ch, __nv_bfloat16* __restrict__ Cl,
         int K, int lda, int ldb, int ldc,
         long long sA, long long sB, long long sC, int bDiv)
{
    extern __shared__ char dsm[];
    const int tid = threadIdx.x;
    const int wid = tid >> 5;
    const int lane = tid & 31;
    const int row0 = blockIdx.y * 128;
    const int col0 = blockIdx.x * 128;

    if (CAUSAL == 1 && col0 >= row0 + 128) return;   // fully masked: never read

    const long long z = blockIdx.z;
    Ah += z * sA;  Al += z * sA;
    Bh += (z / bDiv) * sB;  Bl += (z / bDiv) * sB;

    const uint32_t raw = smem_u32(dsm);
    const uint32_t sb0 = (raw + 1023) & ~1023u;

    int nCh = K >> 6;
    if (CAUSAL == 2) { int lim = (row0 >> 6) + 2; if (lim < nCh) nCh = lim; }

    float acc[4][4][4];
    #pragma unroll
    for (int a = 0; a < 4; a++)
        #pragma unroll
        for (int b = 0; b < 4; b++)
            #pragma unroll
            for (int c = 0; c < 4; c++) acc[a][b][c] = 0.0f;

    const int m0w = (wid & 1) * 64;
    const int n0w = (wid >> 1) * 32;
    const int aRowL = lane & 15;
    const int aColL = (lane >> 4) << 3;
    const int bRowL = (lane & 7) + ((lane >> 4) << 3);
    const int bColL = ((lane >> 3) & 1) << 3;

    // ---- stage loader: 4 arrays x 128 rows x 64 bf16 (128B rows, SW128 swizzle)
    auto issue = [&](int ic) {
        const int k0 = ic << 6;
        const uint32_t st = sb0 + (ic & 1) * STAGE_B;
        #pragma unroll
        for (int i = 0; i < 4; i++) {
            int t = tid + i * 256;
            int r = t >> 3, chn = t & 7;
            uint32_t off = (uint32_t)(r * 128 + chn * 16);
            off ^= (off >> 3) & 0x70;
            long long ga = (long long)(row0 + r) * lda + k0 + chn * 8;
            long long gb = (long long)(col0 + r) * ldb + k0 + chn * 8;
            ldgsts16(st + off,         Ah + ga);
            ldgsts16(st + 16384 + off, Al + ga);
            ldgsts16(st + 32768 + off, Bh + gb);
            ldgsts16(st + 49152 + off, Bl + gb);
        }
    };

    issue(0);
    asm volatile("cp.async.commit_group;" ::: "memory");

    for (int ic = 0; ic < nCh; ic++) {
        if (ic + 1 < nCh) issue(ic + 1);
        asm volatile("cp.async.commit_group;" ::: "memory");
        asm volatile("cp.async.wait_group 1;" ::: "memory");
        __syncthreads();

        const uint32_t st = sb0 + (ic & 1) * STAGE_B;
        #pragma unroll
        for (int ks = 0; ks < 4; ks++) {
            const int k0e = ks * 16;
            uint32_t ah[4][4], al[4][4], bh[2][4], bl[2][4];
            #pragma unroll
            for (int mt = 0; mt < 4; mt++) {
                uint32_t off = (uint32_t)((m0w + mt * 16 + aRowL) * 128 + (k0e + aColL) * 2);
                off ^= (off >> 3) & 0x70;
                ldsm4(ah[mt], st + off);
            }
            #pragma unroll
            for (int p = 0; p < 2; p++) {
                uint32_t off = (uint32_t)((n0w + p * 16 + bRowL) * 128 + (k0e + bColL) * 2);
                off ^= (off >> 3) & 0x70;
                ldsm4(bh[p], st + 32768 + off);
            }
            #pragma unroll
            for (int mt = 0; mt < 4; mt++)
                #pragma unroll
                for (int nt = 0; nt < 4; nt++)
                    mma16816(acc[mt][nt], ah[mt], &bh[nt >> 1][(nt & 1) * 2]);
            #pragma unroll
            for (int p = 0; p < 2; p++) {
                uint32_t off = (uint32_t)((n0w + p * 16 + bRowL) * 128 + (k0e + bColL) * 2);
                off ^= (off >> 3) & 0x70;
                ldsm4(bl[p], st + 49152 + off);
            }
            #pragma unroll
            for (int mt = 0; mt < 4; mt++)
                #pragma unroll
                for (int nt = 0; nt < 4; nt++)
                    mma16816(acc[mt][nt], ah[mt], &bl[nt >> 1][(nt & 1) * 2]);
            #pragma unroll
            for (int mt = 0; mt < 4; mt++) {
                uint32_t off = (uint32_t)((m0w + mt * 16 + aRowL) * 128 + (k0e + aColL) * 2);
                off ^= (off >> 3) & 0x70;
                ldsm4(al[mt], st + 16384 + off);
            }
            #pragma unroll
            for (int mt = 0; mt < 4; mt++)
                #pragma unroll
                for (int nt = 0; nt < 4; nt++)
                    mma16816(acc[mt][nt], al[mt], &bh[nt >> 1][(nt & 1) * 2]);
        }
        __syncthreads();
    }

    // ---- register epilogue
    if (EPI <= 1) C += z * sC;
    else { Ch += z * sC; Cl += z * sC; }

    #pragma unroll
    for (int mt = 0; mt < 4; mt++) {
        #pragma unroll
        for (int nt = 0; nt < 4; nt++) {
            const int r = row0 + m0w + mt * 16 + (lane >> 2);
            const int c = col0 + n0w + nt * 8 + (lane & 3) * 2;
            float d0 = acc[mt][nt][0], d1 = acc[mt][nt][1];
            float d2 = acc[mt][nt][2], d3 = acc[mt][nt][3];
            if (EPI == 1) {
                d0 = SOFT_CAP * tanhf(d0 * (ATTN_SCALE / SOFT_CAP));
                d1 = SOFT_CAP * tanhf(d1 * (ATTN_SCALE / SOFT_CAP));
                d2 = SOFT_CAP * tanhf(d2 * (ATTN_SCALE / SOFT_CAP));
                d3 = SOFT_CAP * tanhf(d3 * (ATTN_SCALE / SOFT_CAP));
            }
            if (EPI <= 1) {
                *reinterpret_cast<float2*>(C + (long long)r * ldc + c)       = make_float2(d0, d1);
                *reinterpret_cast<float2*>(C + (long long)(r + 8) * ldc + c) = make_float2(d2, d3);
            } else {
                __nv_bfloat16 h0 = __float2bfloat16(d0), h1 = __float2bfloat16(d1);
                __nv_bfloat16 h2 = __float2bfloat16(d2), h3 = __float2bfloat16(d3);
                __nv_bfloat162 hv0(h0, h1), hv1(h2, h3);
                __nv_bfloat162 lv0(__float2bfloat16(d0 - __bfloat162float(h0)),
                                   __float2bfloat16(d1 - __bfloat162float(h1)));
                __nv_bfloat162 lv1(__float2bfloat16(d2 - __bfloat162float(h2)),
                                   __float2bfloat16(d3 - __bfloat162float(h3)));
                *reinterpret_cast<__nv_bfloat162*>(Ch + (long long)r * ldc + c)       = hv0;
                *reinterpret_cast<__nv_bfloat162*>(Cl + (long long)r * ldc + c)       = lv0;
                *reinterpret_cast<__nv_bfloat162*>(Ch + (long long)(r + 8) * ldc + c) = hv1;
                *reinterpret_cast<__nv_bfloat162*>(Cl + (long long)(r + 8) * ldc + c) = lv1;
            }
        }
    }
}

// ---------------------------------------------------------------------------
// fp32 -> (hi, lo) bf16 split, elementwise
// ---------------------------------------------------------------------------
__global__ void __launch_bounds__(256)
convsplit(const float4* __restrict__ x, __nv_bfloat162* __restrict__ hi,
          __nv_bfloat162* __restrict__ lo, long long n4)
{
    long long i = (long long)blockIdx.x * 256 + threadIdx.x;
    if (i >= n4) return;
    float4 v = x[i];
    __nv_bfloat16 h0 = __float2bfloat16(v.x), h1 = __float2bfloat16(v.y);
    __nv_bfloat16 h2 = __float2bfloat16(v.z), h3 = __float2bfloat16(v.w);
    hi[2 * i]     = __nv_bfloat162(h0, h1);
    hi[2 * i + 1] = __nv_bfloat162(h2, h3);
    lo[2 * i]     = __nv_bfloat162(__float2bfloat16(v.x - __bfloat162float(h0)),
                                   __float2bfloat16(v.y - __bfloat162float(h1)));
    lo[2 * i + 1] = __nv_bfloat162(__float2bfloat16(v.z - __bfloat162float(h2)),
                                   __float2bfloat16(v.w - __bfloat162float(h3)));
}

// ---------------------------------------------------------------------------
// Transpose + split: in[R,C] fp32 (ldin) -> out[C,R] (hi, lo) bf16 (ldout)
// ---------------------------------------------------------------------------
__global__ void __launch_bounds__(256)
tsplit(const float* __restrict__ in, int ldin, __nv_bfloat16* __restrict__ oh,
       __nv_bfloat16* __restrict__ ol, int ldout)
{
    __shared__ float t[32][33];
    int bx = blockIdx.x * 32, by = blockIdx.y * 32;
    int tx = threadIdx.x, ty = threadIdx.y;
    #pragma unroll
    for (int j = ty; j < 32; j += 8)
        t[j][tx] = in[(long long)(by + j) * ldin + bx + tx];
    __syncthreads();
    #pragma unroll
    for (int j = ty; j < 32; j += 8) {
        float v = t[tx][j];
        __nv_bfloat16 h = __float2bfloat16(v);
        long long o = (long long)(bx + j) * ldout + by + tx;
        oh[o] = h;
        ol[o] = __float2bfloat16(v - __bfloat162float(h));
    }
}

// ---------------------------------------------------------------------------
// Fused RoPE + split: reads fp32 qkv (Q,K region), writes split bf16 pair
// ---------------------------------------------------------------------------
__global__ void __launch_bounds__(256)
rope_split(const float* __restrict__ qkv, const int* __restrict__ positions,
           __nv_bfloat16* __restrict__ oh, __nv_bfloat16* __restrict__ ol)
{
    int idx = blockIdx.x * blockDim.x + threadIdx.x;
    int i = idx & 127;
    int h = (idx >> 7) % (NH + NKV);
    int t = idx / (128 * (NH + NKV));
    if (t >= T_SEQ) return;
    float pos = (float)positions[t];
    float inv = powf(10000.0f, -((2.0f * (float)i) / (float)HD));
    float f = pos * inv;
    float c, s;
    sincosf(f, &s, &c);
    long long base = (long long)t * QKV_COLS + h * HD;   // h<24 covers Q then K region
    float x1 = qkv[base + i], x2 = qkv[base + i + HD / 2];
    float y1 = x1 * c - x2 * s;
    float y2 = x2 * c + x1 * s;
    __nv_bfloat16 h1 = __float2bfloat16(y1);
    __nv_bfloat16 h2 = __float2bfloat16(y2);
    oh[base + i]          = h1;
    ol[base + i]          = __float2bfloat16(y1 - __bfloat162float(h1));
    oh[base + i + HD / 2] = h2;
    ol[base + i + HD / 2] = __float2bfloat16(y2 - __bfloat162float(h2));
}

// ---------------------------------------------------------------------------
// Causal softmax, single global read (registers cache the row),
// __expf (MUFU), split probs zero-padded to the 128-tile boundary.
// ---------------------------------------------------------------------------
__global__ void __launch_bounds__(256)
softmax3(const float* __restrict__ s, __nv_bfloat16* __restrict__ ph,
         __nv_bfloat16* __restrict__ pl)
{
    const int q = blockIdx.x;
    long long ro = ((long long)blockIdx.y * T_SEQ + q) * (long long)T_SEQ;
    const int len = q + 1;
    const int padEnd = ((q >> 7) + 1) << 7;
    const int tid = threadIdx.x, lane = tid & 31, wid = tid >> 5;
    __shared__ float red[8];

    float v[8];
    #pragma unroll
    for (int j = 0; j < 8; j++) {
        int i = tid + j * 256;
        v[j] = (i < len) ? s[ro + i] : NEG_INF;
    }
    float m = NEG_INF;
    #pragma unroll
    for (int j = 0; j < 8; j++) m = fmaxf(m, v[j]);
    #pragma unroll
    for (int o = 16; o; o >>= 1) m = fmaxf(m, __shfl_xor_sync(0xffffffffu, m, o));
    if (lane == 0) red[wid] = m;
    __syncthreads();
    if (tid < 8) {
        float x = red[tid];
        #pragma unroll
        for (int o = 4; o; o >>= 1) x = fmaxf(x, __shfl_xor_sync(0xffu, x, o));
        if (tid == 0) red[0] = x;
    }
    __syncthreads();
    m = red[0];
    __syncthreads();

    float e[8];
    float sum = 0.0f;
    #pragma unroll
    for (int j = 0; j < 8; j++) {
        e[j] = (v[j] == NEG_INF) ? 0.0f : __expf(v[j] - m);
        sum += e[j];
    }
    #pragma unroll
    for (int o = 16; o; o >>= 1) sum += __shfl_xor_sync(0xffffffffu, sum, o);
    if (lane == 0) red[wid] = sum;
    __syncthreads();
    if (tid < 8) {
        float x = red[tid];
        #pragma unroll
        for (int o = 4; o; o >>= 1) x += __shfl_xor_sync(0xffu, x, o);
        if (tid == 0) red[0] = x;
    }
    __syncthreads();
    float inv = 1.0f / red[0];

    #pragma unroll
    for (int j = 0; j < 8; j++) {
        int i = tid + j * 256;
        if (i < padEnd) {
            float p = e[j] * inv;                 // 0 beyond len
            __nv_bfloat16 h = __float2bfloat16(p);
            ph[ro + i] = h;
            pl[ro + i] = __float2bfloat16(p - __bfloat162float(h));
        }
    }
}

// ---------------------------------------------------------------------------
// kernel_launch — graph-capturable, allocation-free
// ---------------------------------------------------------------------------
extern "C" void kernel_launch(void* const* d_in, const int* in_sizes, int n_in,
                              void* d_out, int out_size)
{
    const int*   positions = (const int*)  d_in[0];
    const float* hidden    = (const float*)d_in[1];
    const float* w_qkv     = (const float*)d_in[2];
    const float* w_o       = (const float*)d_in[3];
    float*       out       = (float*)d_out;

    float *qkv, *scores;
    __nv_bfloat16 *hch, *hcl, *wqh, *wql, *woh, *wol, *qch, *qcl, *vch, *vcl, *pph, *ppl, *ach, *acl;
    cudaGetSymbolAddress((void**)&qkv,    g_qkv);
    cudaGetSymbolAddress((void**)&scores, g_scores);
    cudaGetSymbolAddress((void**)&hch, g_hc_h);    cudaGetSymbolAddress((void**)&hcl, g_hc_l);
    cudaGetSymbolAddress((void**)&wqh, g_wqkvT_h); cudaGetSymbolAddress((void**)&wql, g_wqkvT_l);
    cudaGetSymbolAddress((void**)&woh, g_woT_h);   cudaGetSymbolAddress((void**)&wol, g_woT_l);
    cudaGetSymbolAddress((void**)&qch, g_qkvc_h);  cudaGetSymbolAddress((void**)&qcl, g_qkvc_l);
    cudaGetSymbolAddress((void**)&vch, g_vTc_h);   cudaGetSymbolAddress((void**)&vcl, g_vTc_l);
    cudaGetSymbolAddress((void**)&pph, g_p_h);     cudaGetSymbolAddress((void**)&ppl, g_p_l);
    cudaGetSymbolAddress((void**)&ach, g_attnc_h); cudaGetSymbolAddress((void**)&acl, g_attnc_l);

    cudaFuncSetAttribute(gemm_mma<0, 0>, cudaFuncAttributeMaxDynamicSharedMemorySize, GEMM_SMEM);
    cudaFuncSetAttribute(gemm_mma<1, 1>, cudaFuncAttributeMaxDynamicSharedMemorySize, GEMM_SMEM);
    cudaFuncSetAttribute(gemm_mma<2, 2>, cudaFuncAttributeMaxDynamicSharedMemorySize, GEMM_SMEM);

    // Operand prep: weight transposes + hidden split
    tsplit<<<dim3(QKV_COLS / 32, HID / 32), dim3(32, 8)>>>(w_qkv, QKV_COLS, wqh, wql, HID);
    tsplit<<<dim3(HID / 32, ATTN_COLS / 32), dim3(32, 8)>>>(w_o, HID, woh, wol, ATTN_COLS);
    {
        long long n4 = (long long)T_SEQ * HID / 4;
        convsplit<<<(unsigned)((n4 + 255) / 256), 256>>>((const float4*)hidden,
            (__nv_bfloat162*)hch, (__nv_bfloat162*)hcl, n4);
    }

    // 1) QKV projection -> fp32 qkv
    gemm_mma<0, 0><<<dim3(QKV_COLS / 128, T_SEQ / 128, 1), 256, GEMM_SMEM>>>(
        hch, hcl, wqh, wql, qkv, nullptr, nullptr,
        HID, HID, HID, QKV_COLS, 0, 0, 0, 1);

    // 2) fused RoPE + split on Q,K;  transpose+split V
    rope_split<<<(T_SEQ * (NH + NKV) * (HD / 2)) / 256, 256>>>(qkv, positions, qch, qcl);
    tsplit<<<dim3((NKV * HD) / 32, T_SEQ / 32), dim3(32, 8)>>>(qkv + V_OFF, QKV_COLS, vch, vcl, T_SEQ);

    // 3) scores[h] = softcap(scale * Q_h K_{h/2}^T), upper tiles skipped
    gemm_mma<1, 1><<<dim3(T_SEQ / 128, T_SEQ / 128, NH), 256, GEMM_SMEM>>>(
        qch, qcl, qch + K_OFF, qcl + K_OFF, scores, nullptr, nullptr,
        HD, QKV_COLS, QKV_COLS, T_SEQ,
        (long long)HD, (long long)HD, (long long)T_SEQ * T_SEQ, 2);

    // 4) causal softmax -> split probs (zero-padded to tile boundary)
    softmax3<<<dim3(T_SEQ, NH), 256>>>(scores, pph, ppl);

    // 5) attn[h] = P_h @ V_{h/2}, K truncated at diagonal; direct split store
    gemm_mma<2, 2><<<dim3(HD / 128, T_SEQ / 128, NH), 256, GEMM_SMEM>>>(
        pph, ppl, vch, vcl, nullptr, ach, acl,
        T_SEQ, T_SEQ, T_SEQ, ATTN_COLS,
        (long long)T_SEQ * T_SEQ, (long long)HD * T_SEQ, (long long)HD, 2);

    // 6) output projection
    gemm_mma<0, 0><<<dim3(HID / 128, T_SEQ / 128, 1), 256, GEMM_SMEM>>>(
        ach, acl, woh, wol, out, nullptr, nullptr,
        ATTN_COLS, ATTN_COLS, ATTN_COLS, HID, 0, 0, 0, 1);
}